// round 11
// baseline (speedup 1.0000x reference)
#include <cuda_runtime.h>
#include <cuda_fp16.h>
#include <cstdint>

// ---------------------------------------------------------------- constants
#define EPSV 0.007f
#define NPIX 25088              // 32*28*28 = 196 * 128
#define KA   1152
#define KB   2432               // 9*256 + 128 shortcut
#define NKA  36
#define NKB  76

#define ROWB      80            // padded bytes per 32-fp16 k-row
#define OFF_B     10240         // A: 128 rows * 80B, then B: 128 rows * 80B
#define STAGE_SZ  20480
#define NSTG      3
#define B_TILE_BYTES 10240
#define DYN_SMEM  67584         // max(3*STAGE_SZ=61440, epilogue 128*132*4=67584)

// ---------------------------------------------------------------- globals
__device__ __align__(256) __half g_xhi[(size_t)32 * 56 * 56 * 128];
__device__ __align__(256) __half g_yhi[(size_t)NPIX * 256];
__device__ __align__(256) float g_xs2[32 * 56 * 56];
__device__ __align__(256) float g_psq[NPIX];
// k-blocked weights: [kb][half][128 rows][40 halfs]  (first 32 real, 8 pad)
__device__ __align__(256) __half g_wA2[NKA * 2 * 128 * 40];
__device__ __align__(256) __half g_wB2[NKB * 2 * 128 * 40];
__device__ __align__(256) float g_wsq[256];

// ---------------------------------------------------------------- ptx utils
__device__ __forceinline__ uint32_t smem_u32(const void* p) {
    return (uint32_t)__cvta_generic_to_shared(p);
}
__device__ __forceinline__ void cpa16(uint32_t dst, const void* src, uint32_t sz) {
    asm volatile("cp.async.cg.shared.global [%0], [%1], 16, %2;"
                 :: "r"(dst), "l"(src), "r"(sz) : "memory");
}
#define CP_COMMIT() asm volatile("cp.async.commit_group;" ::: "memory")
#define CP_WAIT1()  asm volatile("cp.async.wait_group 1;" ::: "memory")

__device__ __forceinline__ void bulk_cp(uint32_t dst, const void* src,
                                        uint32_t bytes, uint32_t mbar) {
    asm volatile(
        "cp.async.bulk.shared::cluster.global.mbarrier::complete_tx::bytes "
        "[%0], [%1], %2, [%3];"
        :: "r"(dst), "l"(src), "r"(bytes), "r"(mbar) : "memory");
}
#define MBAR_INIT(mb, c) asm volatile("mbarrier.init.shared.b64 [%0], %1;" :: "r"(mb), "r"(c) : "memory")
#define MBAR_EXPECT_TX(mb, b) asm volatile("mbarrier.arrive.expect_tx.shared.b64 _, [%0], %1;" :: "r"(mb), "r"(b) : "memory")

__device__ __forceinline__ void mbar_wait(uint32_t mb, uint32_t parity) {
    uint32_t done;
    asm volatile(
        "{\n\t.reg .pred p;\n\t"
        "mbarrier.try_wait.parity.acquire.cta.shared::cta.b64 p, [%1], %2;\n\t"
        "selp.b32 %0, 1, 0, p;\n\t}"
        : "=r"(done) : "r"(mb), "r"(parity) : "memory");
    if (!done) {
        asm volatile(
            "{\n\t.reg .pred P1;\n\t"
            "WL_%=:\n\t"
            "mbarrier.try_wait.parity.acquire.cta.shared::cta.b64 P1, [%0], %1, 0x989680;\n\t"
            "@P1 bra.uni WD_%=;\n\t"
            "bra.uni WL_%=;\n\t"
            "WD_%=:\n\t}"
            :: "r"(mb), "r"(parity) : "memory");
    }
}

#define LDSM4(r0, r1, r2, r3, addr) \
    asm volatile("ldmatrix.sync.aligned.m8n8.x4.shared.b16 {%0,%1,%2,%3}, [%4];" \
                 : "=r"(r0), "=r"(r1), "=r"(r2), "=r"(r3) : "r"(addr))

#define MMAF16(C, A, B0, B1) \
    asm volatile("mma.sync.aligned.m16n8k16.row.col.f32.f16.f16.f32 " \
                 "{%0,%1,%2,%3}, {%4,%5,%6,%7}, {%8,%9}, {%0,%1,%2,%3};" \
                 : "+f"((C)[0]), "+f"((C)[1]), "+f"((C)[2]), "+f"((C)[3]) \
                 : "r"((A)[0]), "r"((A)[1]), "r"((A)[2]), "r"((A)[3]), \
                   "r"(B0), "r"(B1))

// ---------------------------------------------------------------- prep
__global__ __launch_bounds__(256) void prep_x(const float* __restrict__ x) {
    __shared__ float s[128][57];
    __shared__ float s2p[56][4];
    const int h = blockIdx.x, n = blockIdx.y;
    const float* xb = x + ((size_t)n * 128 * 56 + h) * 56;
    for (int idx = threadIdx.x; idx < 128 * 56; idx += 256) {
        int ci = idx / 56, wi = idx - 56 * ci;
        s[ci][wi] = xb[(size_t)ci * 3136 + wi];
    }
    __syncthreads();
    for (int idx = threadIdx.x; idx < 56 * 128; idx += 256) {
        int wi = idx >> 7, ci = idx & 127;
        g_xhi[((size_t)(n * 56 + h) * 56 + wi) * 128 + ci] = __float2half(s[ci][wi]);
    }
    if (threadIdx.x < 224) {
        int wi = threadIdx.x >> 2, q = threadIdx.x & 3;
        float a = 0.f;
        for (int ci = q * 32; ci < q * 32 + 32; ci++) { float v = s[ci][wi]; a += v * v; }
        s2p[wi][q] = a;
    }
    __syncthreads();
    if (threadIdx.x < 56) {
        int wi = threadIdx.x;
        g_xs2[(n * 56 + h) * 56 + wi] = s2p[wi][0] + s2p[wi][1] + s2p[wi][2] + s2p[wi][3];
    }
}

__global__ void prep_psq() {
    const int pw = threadIdx.x, ph = blockIdx.x, n = blockIdx.y;
    float s = 0.f;
    for (int dr = -1; dr <= 1; dr++) {
        int r = 2 * ph + dr;
        if ((unsigned)r >= 56) continue;
        for (int dc = -1; dc <= 1; dc++) {
            int c = 2 * pw + dc;
            if ((unsigned)c >= 56) continue;
            s += g_xs2[(n * 56 + r) * 56 + c];
        }
    }
    g_psq[(n * 28 + ph) * 28 + pw] = s;
}

// w_yat [co][ci][3][3] -> g_wA2[kb][co>>7][co&127][j] fp16 (k=kb*32+j), + wsq
__global__ __launch_bounds__(256) void prep_wA(const float* __restrict__ w) {
    __shared__ float red[256];
    const int co = blockIdx.x;
    const int half = co >> 7, r = co & 127;
    float acc = 0.f;
    for (int k = threadIdx.x; k < KA; k += 256) {
        int kh = k / 384, rem = k - kh * 384, kw = rem >> 7, ci = rem & 127;
        float v = w[(size_t)co * KA + ci * 9 + kh * 3 + kw];
        int kb = k >> 5, j = k & 31;
        g_wA2[((kb * 2 + half) * 128 + r) * 40 + j] = __float2half(v);
        acc += v * v;
    }
    for (int idx = threadIdx.x; idx < NKA * 8; idx += 256) {
        int kb = idx >> 3, j = 32 + (idx & 7);
        g_wA2[((kb * 2 + half) * 128 + r) * 40 + j] = __float2half(0.f);
    }
    red[threadIdx.x] = acc;
    __syncthreads();
    for (int o = 128; o > 0; o >>= 1) {
        if (threadIdx.x < o) red[threadIdx.x] += red[threadIdx.x + o];
        __syncthreads();
    }
    if (threadIdx.x == 0) g_wsq[co] = red[0];
}

__global__ __launch_bounds__(256) void prep_wB(const float* __restrict__ wl,
                                               const float* __restrict__ ws) {
    const int co = blockIdx.x;
    const int half = co >> 7, r = co & 127;
    for (int k = threadIdx.x; k < KB; k += 256) {
        float v;
        if (k < 2304) {
            int kh = k / 768, rem = k - kh * 768, kw = rem >> 8, ci = rem & 255;
            v = wl[(size_t)co * 2304 + ci * 9 + kh * 3 + kw];
        } else {
            v = ws[co * 128 + (k - 2304)];
        }
        int kb = k >> 5, j = k & 31;
        g_wB2[((kb * 2 + half) * 128 + r) * 40 + j] = __float2half(v);
    }
    for (int idx = threadIdx.x; idx < NKB * 8; idx += 256) {
        int kb = idx >> 3, j = 32 + (idx & 7);
        g_wB2[((kb * 2 + half) * 128 + r) * 40 + j] = __float2half(0.f);
    }
}

// ---------------------------------------------------------------- A fill (cp.async)
__device__ __forceinline__ void fill_A(int stage, int kb, uint32_t sbuf,
                                       int t, int ctaM) {
#pragma unroll
    for (int j = 0; j < 2; j++) {
        const int idx = t + 256 * j;
        const int ch  = idx & 3;
        const int row = idx >> 2;
        const int p   = ctaM * 128 + row;
        const int n   = p / 784;
        const int rem = p - n * 784;
        const int ph  = rem / 28;
        const int pw  = rem - ph * 28;
        const __half* src;
        uint32_t ok;
        if (stage == 0) {
            int tap = kb >> 2, kh = tap / 3, kw = tap - 3 * (tap / 3);
            int ci0 = (kb & 3) * 32;
            int r = 2 * ph - 1 + kh, c = 2 * pw - 1 + kw;
            bool v = ((unsigned)r < 56) && ((unsigned)c < 56);
            size_t off = v ? ((size_t)((n * 56 + r) * 56 + c) * 128 + ci0) : 0;
            src = g_xhi + off; ok = v ? 16u : 0u;
        } else if (kb < 72) {
            int tap = kb >> 3, kh = tap / 3, kw = tap - 3 * (tap / 3);
            int co0 = (kb & 7) * 32;
            int r = ph - 1 + kh, c = pw - 1 + kw;
            bool v = ((unsigned)r < 28) && ((unsigned)c < 28);
            size_t off = v ? ((size_t)((n * 28 + r) * 28 + c) * 256 + co0) : 0;
            src = g_yhi + off; ok = v ? 16u : 0u;
        } else {
            int ci0 = (kb - 72) * 32;
            size_t off = (size_t)((n * 56 + 2 * ph) * 56 + 2 * pw) * 128 + ci0;
            src = g_xhi + off; ok = 16u;
        }
        cpa16(sbuf + row * ROWB + ch * 16, (const char*)src + ch * 16, ok);
    }
}

// ---------------------------------------------------------------- GEMM kernel
// CTA 128 px x 128 co; 8 warps 4(m) x 2(n); warp tile 32 x 64; 3-stage.
// A via cp.async.cg (zero-fill halo); B via single cp.async.bulk + mbarrier.
__global__ __launch_bounds__(256, 2)
void gemm_kernel(int stage, const float* __restrict__ alpha, float* __restrict__ out) {
    extern __shared__ __align__(1024) char dsm[];
    __shared__ float s_psq[128];
    __shared__ float s_wsq[128];
    __shared__ __align__(8) uint64_t s_mbar[NSTG];

    const int t    = threadIdx.x;
    const int lane = t & 31;
    const int w    = t >> 5;
    const int wm   = w & 3;
    const int wn   = w >> 2;
    const int ctaM = blockIdx.x;
    const int ctaN = blockIdx.y;
    const uint32_t sdyn = smem_u32(dsm);

    if (t == 0) {
        MBAR_INIT(smem_u32(&s_mbar[0]), 1);
        MBAR_INIT(smem_u32(&s_mbar[1]), 1);
        MBAR_INIT(smem_u32(&s_mbar[2]), 1);
    }
    if (stage == 0 && t < 128) {
        s_psq[t] = g_psq[ctaM * 128 + t];
        s_wsq[t] = g_wsq[ctaN * 128 + t];
    }
    __syncthreads();   // mbar init visible before any expect/bulk/wait

    float acc[2][8][4];
#pragma unroll
    for (int a = 0; a < 2; a++)
#pragma unroll
        for (int b = 0; b < 8; b++)
#pragma unroll
            for (int c = 0; c < 4; c++) acc[a][b][c] = 0.f;

    const uint32_t aOff = (uint32_t)(wm * 32 + (lane & 15)) * ROWB + (lane >> 4) * 16;
    const uint32_t bOff = (uint32_t)(wn * 64 + (lane & 7) + ((lane >> 4) << 3)) * ROWB
                        + ((lane >> 3) & 1) * 16;

    const int NK = stage ? NKB : NKA;
    const __half* wsrc = stage ? g_wB2 : g_wA2;

    // prologue: 2 k-blocks in flight
    fill_A(stage, 0, sdyn, t, ctaM);             CP_COMMIT();
    fill_A(stage, 1, sdyn + STAGE_SZ, t, ctaM);  CP_COMMIT();
    if (t == 0) {
#pragma unroll
        for (int i = 0; i < 2; i++) {
            uint32_t mb = smem_u32(&s_mbar[i]);
            MBAR_EXPECT_TX(mb, B_TILE_BYTES);
            bulk_cp(sdyn + i * STAGE_SZ + OFF_B,
                    wsrc + (size_t)(i * 2 + ctaN) * (128 * 40), B_TILE_BYTES, mb);
        }
    }

    int buf = 0;
    uint32_t p0 = 0, p1 = 0, p2 = 0;
    for (int kb = 0; kb < NK; kb++) {
        CP_WAIT1();                                    // A of kb complete
        {                                              // B of kb complete
            uint32_t pr = (buf == 0) ? p0 : (buf == 1) ? p1 : p2;
            mbar_wait(smem_u32(&s_mbar[buf]), pr);
            if (buf == 0) p0 ^= 1; else if (buf == 1) p1 ^= 1; else p2 ^= 1;
        }
        __syncthreads();                               // compute(kb-1) fully done

        if (kb + 2 < NK) {
            int nb = buf + 2; if (nb >= NSTG) nb -= NSTG;
            fill_A(stage, kb + 2, sdyn + nb * STAGE_SZ, t, ctaM);
            if (t == 0) {
                uint32_t mb = smem_u32(&s_mbar[nb]);
                MBAR_EXPECT_TX(mb, B_TILE_BYTES);
                bulk_cp(sdyn + nb * STAGE_SZ + OFF_B,
                        wsrc + (size_t)((kb + 2) * 2 + ctaN) * (128 * 40),
                        B_TILE_BYTES, mb);
            }
        }
        CP_COMMIT();

        const uint32_t sb = sdyn + buf * STAGE_SZ;
#pragma unroll
        for (int kc = 0; kc < 2; kc++) {
            const uint32_t kByte = kc * 32;
            uint32_t ah[2][4];
#pragma unroll
            for (int im = 0; im < 2; im++) {
                uint32_t addr = sb + aOff + im * (16 * ROWB) + kByte;
                LDSM4(ah[im][0], ah[im][1], ah[im][2], ah[im][3], addr);
            }
#pragma unroll
            for (int ip16 = 0; ip16 < 4; ip16++) {
                uint32_t baddr = sb + OFF_B + bOff + ip16 * (16 * ROWB) + kByte;
                uint32_t b0, b1, b2, b3;
                LDSM4(b0, b1, b2, b3, baddr);
#pragma unroll
                for (int im = 0; im < 2; im++) {
                    MMAF16(acc[im][2 * ip16],     ah[im], b0, b1);
                    MMAF16(acc[im][2 * ip16 + 1], ah[im], b2, b3);
                }
            }
        }
        if (++buf == NSTG) buf = 0;
    }
    __syncthreads();

    // ---------------- epilogue ----------------
    if (stage == 0) {
        const float scale = powf(16.0f / logf(257.0f), alpha[0]);
#pragma unroll
        for (int im = 0; im < 2; im++) {
#pragma unroll
            for (int ip8 = 0; ip8 < 8; ip8++) {
                const int cl = wn * 64 + ip8 * 8 + 2 * (lane & 3);
                const float wq0 = s_wsq[cl], wq1 = s_wsq[cl + 1];
                const float* c = acc[im][ip8];
#pragma unroll
                for (int s = 0; s < 2; s++) {
                    const int pl = wm * 32 + im * 16 + (lane >> 2) + 8 * s;
                    const int p  = ctaM * 128 + pl;
                    const float psqv = s_psq[pl];
                    const float f0 = c[2 * s], f1 = c[2 * s + 1];
                    const float y0 = scale * f0 * f0 / (psqv + wq0 - 2.f * f0 + EPSV);
                    const float y1 = scale * f1 * f1 / (psqv + wq1 - 2.f * f1 + EPSV);
                    const size_t oi = (size_t)p * 128 + ((ctaN * 128 + cl) >> 1);
                    ((uint32_t*)g_yhi)[oi] =
                        (uint32_t)__half_as_ushort(__float2half(y0)) |
                        ((uint32_t)__half_as_ushort(__float2half(y1)) << 16);
                }
            }
        }
    } else {
        float* sy = (float*)dsm;
#pragma unroll
        for (int im = 0; im < 2; im++) {
#pragma unroll
            for (int ip8 = 0; ip8 < 8; ip8++) {
                const int cl = wn * 64 + ip8 * 8 + 2 * (lane & 3);
                const float* c = acc[im][ip8];
#pragma unroll
                for (int s = 0; s < 2; s++) {
                    const int pl = wm * 32 + im * 16 + (lane >> 2) + 8 * s;
                    sy[cl * 132 + pl]       = c[2 * s];
                    sy[(cl + 1) * 132 + pl] = c[2 * s + 1];
                }
            }
        }
        __syncthreads();
        for (int i = t; i < 128 * 128; i += 256) {
            const int col = i >> 7, q = i & 127;
            const int p = ctaM * 128 + q;
            const int n = p / 784, rem = p - n * 784;
            out[(size_t)n * 200704 + (size_t)(ctaN * 128 + col) * 784 + rem] =
                sy[col * 132 + q];
        }
    }
}

// ---------------------------------------------------------------- launch
extern "C" void kernel_launch(void* const* d_in, const int* in_sizes, int n_in,
                              void* d_out, int out_size) {
    const float* x       = (const float*)d_in[0];
    const float* w_yat   = (const float*)d_in[1];
    const float* alpha   = (const float*)d_in[2];
    const float* w_lin   = (const float*)d_in[3];
    const float* w_short = (const float*)d_in[4];
    float* out = (float*)d_out;

    cudaFuncSetAttribute(gemm_kernel, cudaFuncAttributeMaxDynamicSharedMemorySize, DYN_SMEM);

    prep_x  <<<dim3(56, 32), 256>>>(x);
    prep_psq<<<dim3(28, 32), 28>>>();
    prep_wA <<<256, 256>>>(w_yat);
    prep_wB <<<256, 256>>>(w_lin, w_short);

    dim3 grid(196, 2);
    gemm_kernel<<<grid, 256, DYN_SMEM>>>(0, alpha, out);   // YAT -> g_yhi
    gemm_kernel<<<grid, 256, DYN_SMEM>>>(1, alpha, out);   // lin + shortcut -> out
}

// round 12
// speedup vs baseline: 1.0068x; 1.0068x over previous
#include <cuda_runtime.h>
#include <cuda_fp16.h>
#include <cstdint>

// ---------------------------------------------------------------- constants
#define EPSV 0.007f
#define NPIX 25088              // 32*28*28 = 196 * 128
#define KA   1152
#define KB   2432               // 9*256 + 128 shortcut
#define NKA  36
#define NKB  76

#define ROWB      80            // padded bytes per 32-fp16 k-row
#define OFF_B     10240         // A: 128 rows * 80B, then B: 128 rows * 80B
#define STAGE_SZ  20480
#define NSTG      3
#define B_TILE_BYTES 10240
#define DYN_SMEM  67584         // max(3*STAGE_SZ=61440, epilogue 128*132*4=67584)

// ---------------------------------------------------------------- globals
__device__ __align__(256) __half g_xhi[(size_t)32 * 56 * 56 * 128];
__device__ __align__(256) __half g_yhi[(size_t)NPIX * 256];
__device__ __align__(256) float g_xs2[32 * 56 * 56];
__device__ __align__(256) float g_psq[NPIX];
// k-blocked weights: [kb][half][128 rows][40 halfs]  (first 32 real, 8 pad)
__device__ __align__(256) __half g_wA2[NKA * 2 * 128 * 40];
__device__ __align__(256) __half g_wB2[NKB * 2 * 128 * 40];
__device__ __align__(256) float g_wsq[256];

// ---------------------------------------------------------------- ptx utils
__device__ __forceinline__ uint32_t smem_u32(const void* p) {
    return (uint32_t)__cvta_generic_to_shared(p);
}
__device__ __forceinline__ void cpa16(uint32_t dst, const void* src, uint32_t sz) {
    asm volatile("cp.async.cg.shared.global [%0], [%1], 16, %2;"
                 :: "r"(dst), "l"(src), "r"(sz) : "memory");
}
#define CP_COMMIT() asm volatile("cp.async.commit_group;" ::: "memory")
#define CP_WAIT1()  asm volatile("cp.async.wait_group 1;" ::: "memory")

__device__ __forceinline__ void bulk_cp(uint32_t dst, const void* src,
                                        uint32_t bytes, uint32_t mbar) {
    asm volatile(
        "cp.async.bulk.shared::cluster.global.mbarrier::complete_tx::bytes "
        "[%0], [%1], %2, [%3];"
        :: "r"(dst), "l"(src), "r"(bytes), "r"(mbar) : "memory");
}
#define MBAR_INIT(mb, c) asm volatile("mbarrier.init.shared.b64 [%0], %1;" :: "r"(mb), "r"(c) : "memory")
#define MBAR_EXPECT_TX(mb, b) asm volatile("mbarrier.arrive.expect_tx.shared.b64 _, [%0], %1;" :: "r"(mb), "r"(b) : "memory")

__device__ __forceinline__ void mbar_wait(uint32_t mb, uint32_t parity) {
    uint32_t done;
    asm volatile(
        "{\n\t.reg .pred p;\n\t"
        "mbarrier.try_wait.parity.acquire.cta.shared::cta.b64 p, [%1], %2;\n\t"
        "selp.b32 %0, 1, 0, p;\n\t}"
        : "=r"(done) : "r"(mb), "r"(parity) : "memory");
    if (!done) {
        asm volatile(
            "{\n\t.reg .pred P1;\n\t"
            "WL_%=:\n\t"
            "mbarrier.try_wait.parity.acquire.cta.shared::cta.b64 P1, [%0], %1, 0x989680;\n\t"
            "@P1 bra.uni WD_%=;\n\t"
            "bra.uni WL_%=;\n\t"
            "WD_%=:\n\t}"
            :: "r"(mb), "r"(parity) : "memory");
    }
}

#define LDSM4(r0, r1, r2, r3, addr) \
    asm volatile("ldmatrix.sync.aligned.m8n8.x4.shared.b16 {%0,%1,%2,%3}, [%4];" \
                 : "=r"(r0), "=r"(r1), "=r"(r2), "=r"(r3) : "r"(addr))

#define MMAF16(C, A, B0, B1) \
    asm volatile("mma.sync.aligned.m16n8k16.row.col.f32.f16.f16.f32 " \
                 "{%0,%1,%2,%3}, {%4,%5,%6,%7}, {%8,%9}, {%0,%1,%2,%3};" \
                 : "+f"((C)[0]), "+f"((C)[1]), "+f"((C)[2]), "+f"((C)[3]) \
                 : "r"((A)[0]), "r"((A)[1]), "r"((A)[2]), "r"((A)[3]), \
                   "r"(B0), "r"(B1))

// ---------------------------------------------------------------- prep
__global__ __launch_bounds__(256) void prep_x(const float* __restrict__ x) {
    __shared__ float s[128][57];
    __shared__ float s2p[56][4];
    const int h = blockIdx.x, n = blockIdx.y;
    const float* xb = x + ((size_t)n * 128 * 56 + h) * 56;
    for (int idx = threadIdx.x; idx < 128 * 56; idx += 256) {
        int ci = idx / 56, wi = idx - 56 * ci;
        s[ci][wi] = xb[(size_t)ci * 3136 + wi];
    }
    __syncthreads();
    for (int idx = threadIdx.x; idx < 56 * 128; idx += 256) {
        int wi = idx >> 7, ci = idx & 127;
        g_xhi[((size_t)(n * 56 + h) * 56 + wi) * 128 + ci] = __float2half(s[ci][wi]);
    }
    if (threadIdx.x < 224) {
        int wi = threadIdx.x >> 2, q = threadIdx.x & 3;
        float a = 0.f;
        for (int ci = q * 32; ci < q * 32 + 32; ci++) { float v = s[ci][wi]; a += v * v; }
        s2p[wi][q] = a;
    }
    __syncthreads();
    if (threadIdx.x < 56) {
        int wi = threadIdx.x;
        g_xs2[(n * 56 + h) * 56 + wi] = s2p[wi][0] + s2p[wi][1] + s2p[wi][2] + s2p[wi][3];
    }
}

__global__ void prep_psq() {
    const int pw = threadIdx.x, ph = blockIdx.x, n = blockIdx.y;
    float s = 0.f;
    for (int dr = -1; dr <= 1; dr++) {
        int r = 2 * ph + dr;
        if ((unsigned)r >= 56) continue;
        for (int dc = -1; dc <= 1; dc++) {
            int c = 2 * pw + dc;
            if ((unsigned)c >= 56) continue;
            s += g_xs2[(n * 56 + r) * 56 + c];
        }
    }
    g_psq[(n * 28 + ph) * 28 + pw] = s;
}

// w_yat [co][ci][3][3] -> g_wA2[kb][co>>7][co&127][j] fp16 (k=kb*32+j), + wsq
__global__ __launch_bounds__(256) void prep_wA(const float* __restrict__ w) {
    __shared__ float red[256];
    const int co = blockIdx.x;
    const int half = co >> 7, r = co & 127;
    float acc = 0.f;
    for (int k = threadIdx.x; k < KA; k += 256) {
        int kh = k / 384, rem = k - kh * 384, kw = rem >> 7, ci = rem & 127;
        float v = w[(size_t)co * KA + ci * 9 + kh * 3 + kw];
        int kb = k >> 5, j = k & 31;
        g_wA2[((kb * 2 + half) * 128 + r) * 40 + j] = __float2half(v);
        acc += v * v;
    }
    for (int idx = threadIdx.x; idx < NKA * 8; idx += 256) {
        int kb = idx >> 3, j = 32 + (idx & 7);
        g_wA2[((kb * 2 + half) * 128 + r) * 40 + j] = __float2half(0.f);
    }
    red[threadIdx.x] = acc;
    __syncthreads();
    for (int o = 128; o > 0; o >>= 1) {
        if (threadIdx.x < o) red[threadIdx.x] += red[threadIdx.x + o];
        __syncthreads();
    }
    if (threadIdx.x == 0) g_wsq[co] = red[0];
}

__global__ __launch_bounds__(256) void prep_wB(const float* __restrict__ wl,
                                               const float* __restrict__ ws) {
    const int co = blockIdx.x;
    const int half = co >> 7, r = co & 127;
    for (int k = threadIdx.x; k < KB; k += 256) {
        float v;
        if (k < 2304) {
            int kh = k / 768, rem = k - kh * 768, kw = rem >> 8, ci = rem & 255;
            v = wl[(size_t)co * 2304 + ci * 9 + kh * 3 + kw];
        } else {
            v = ws[co * 128 + (k - 2304)];
        }
        int kb = k >> 5, j = k & 31;
        g_wB2[((kb * 2 + half) * 128 + r) * 40 + j] = __float2half(v);
    }
    for (int idx = threadIdx.x; idx < NKB * 8; idx += 256) {
        int kb = idx >> 3, j = 32 + (idx & 7);
        g_wB2[((kb * 2 + half) * 128 + r) * 40 + j] = __float2half(0.f);
    }
}

// ---------------------------------------------------------------- A fill (cp.async)
__device__ __forceinline__ void fill_A(int stage, int kb, uint32_t sbuf,
                                       int t, int ctaM) {
#pragma unroll
    for (int j = 0; j < 2; j++) {
        const int idx = t + 256 * j;
        const int ch  = idx & 3;
        const int row = idx >> 2;
        const int p   = ctaM * 128 + row;
        const int n   = p / 784;
        const int rem = p - n * 784;
        const int ph  = rem / 28;
        const int pw  = rem - ph * 28;
        const __half* src;
        uint32_t ok;
        if (stage == 0) {
            int tap = kb >> 2, kh = tap / 3, kw = tap - 3 * (tap / 3);
            int ci0 = (kb & 3) * 32;
            int r = 2 * ph - 1 + kh, c = 2 * pw - 1 + kw;
            bool v = ((unsigned)r < 56) && ((unsigned)c < 56);
            size_t off = v ? ((size_t)((n * 56 + r) * 56 + c) * 128 + ci0) : 0;
            src = g_xhi + off; ok = v ? 16u : 0u;
        } else if (kb < 72) {
            int tap = kb >> 3, kh = tap / 3, kw = tap - 3 * (tap / 3);
            int co0 = (kb & 7) * 32;
            int r = ph - 1 + kh, c = pw - 1 + kw;
            bool v = ((unsigned)r < 28) && ((unsigned)c < 28);
            size_t off = v ? ((size_t)((n * 28 + r) * 28 + c) * 256 + co0) : 0;
            src = g_yhi + off; ok = v ? 16u : 0u;
        } else {
            int ci0 = (kb - 72) * 32;
            size_t off = (size_t)((n * 56 + 2 * ph) * 56 + 2 * pw) * 128 + ci0;
            src = g_xhi + off; ok = 16u;
        }
        cpa16(sbuf + row * ROWB + ch * 16, (const char*)src + ch * 16, ok);
    }
}

// ---------------------------------------------------------------- GEMM kernel
// CTA 128 px x 128 co; 8 warps 4(m) x 2(n); warp tile 32 x 64; 3-stage.
// A via cp.async.cg (zero-fill halo); B via single cp.async.bulk + mbarrier.
__global__ __launch_bounds__(256, 2)
void gemm_kernel(int stage, const float* __restrict__ alpha, float* __restrict__ out) {
    extern __shared__ __align__(1024) char dsm[];
    __shared__ float s_psq[128];
    __shared__ float s_wsq[128];
    __shared__ __align__(8) uint64_t s_mbar[NSTG];

    const int t    = threadIdx.x;
    const int lane = t & 31;
    const int w    = t >> 5;
    const int wm   = w & 3;
    const int wn   = w >> 2;
    const int ctaM = blockIdx.x;
    const int ctaN = blockIdx.y;
    const uint32_t sdyn = smem_u32(dsm);

    if (t == 0) {
        MBAR_INIT(smem_u32(&s_mbar[0]), 1);
        MBAR_INIT(smem_u32(&s_mbar[1]), 1);
        MBAR_INIT(smem_u32(&s_mbar[2]), 1);
    }
    if (stage == 0 && t < 128) {
        s_psq[t] = g_psq[ctaM * 128 + t];
        s_wsq[t] = g_wsq[ctaN * 128 + t];
    }
    __syncthreads();   // mbar init visible before any expect/bulk/wait

    float acc[2][8][4];
#pragma unroll
    for (int a = 0; a < 2; a++)
#pragma unroll
        for (int b = 0; b < 8; b++)
#pragma unroll
            for (int c = 0; c < 4; c++) acc[a][b][c] = 0.f;

    const uint32_t aOff = (uint32_t)(wm * 32 + (lane & 15)) * ROWB + (lane >> 4) * 16;
    const uint32_t bOff = (uint32_t)(wn * 64 + (lane & 7) + ((lane >> 4) << 3)) * ROWB
                        + ((lane >> 3) & 1) * 16;

    const int NK = stage ? NKB : NKA;
    const __half* wsrc = stage ? g_wB2 : g_wA2;

    // prologue: 2 k-blocks in flight
    fill_A(stage, 0, sdyn, t, ctaM);             CP_COMMIT();
    fill_A(stage, 1, sdyn + STAGE_SZ, t, ctaM);  CP_COMMIT();
    if (t == 0) {
#pragma unroll
        for (int i = 0; i < 2; i++) {
            uint32_t mb = smem_u32(&s_mbar[i]);
            MBAR_EXPECT_TX(mb, B_TILE_BYTES);
            bulk_cp(sdyn + i * STAGE_SZ + OFF_B,
                    wsrc + (size_t)(i * 2 + ctaN) * (128 * 40), B_TILE_BYTES, mb);
        }
    }

    int buf = 0;
    uint32_t p0 = 0, p1 = 0, p2 = 0;
    for (int kb = 0; kb < NK; kb++) {
        CP_WAIT1();                                    // A of kb complete
        {                                              // B of kb complete
            uint32_t pr = (buf == 0) ? p0 : (buf == 1) ? p1 : p2;
            mbar_wait(smem_u32(&s_mbar[buf]), pr);
            if (buf == 0) p0 ^= 1; else if (buf == 1) p1 ^= 1; else p2 ^= 1;
        }
        __syncthreads();                               // compute(kb-1) fully done

        if (kb + 2 < NK) {
            int nb = buf + 2; if (nb >= NSTG) nb -= NSTG;
            fill_A(stage, kb + 2, sdyn + nb * STAGE_SZ, t, ctaM);
            if (t == 0) {
                uint32_t mb = smem_u32(&s_mbar[nb]);
                MBAR_EXPECT_TX(mb, B_TILE_BYTES);
                bulk_cp(sdyn + nb * STAGE_SZ + OFF_B,
                        wsrc + (size_t)((kb + 2) * 2 + ctaN) * (128 * 40),
                        B_TILE_BYTES, mb);
            }
        }
        CP_COMMIT();

        const uint32_t sb = sdyn + buf * STAGE_SZ;
#pragma unroll
        for (int kc = 0; kc < 2; kc++) {
            const uint32_t kByte = kc * 32;
            uint32_t ah[2][4];
#pragma unroll
            for (int im = 0; im < 2; im++) {
                uint32_t addr = sb + aOff + im * (16 * ROWB) + kByte;
                LDSM4(ah[im][0], ah[im][1], ah[im][2], ah[im][3], addr);
            }
#pragma unroll
            for (int ip16 = 0; ip16 < 4; ip16++) {
                uint32_t baddr = sb + OFF_B + bOff + ip16 * (16 * ROWB) + kByte;
                uint32_t b0, b1, b2, b3;
                LDSM4(b0, b1, b2, b3, baddr);
#pragma unroll
                for (int im = 0; im < 2; im++) {
                    MMAF16(acc[im][2 * ip16],     ah[im], b0, b1);
                    MMAF16(acc[im][2 * ip16 + 1], ah[im], b2, b3);
                }
            }
        }
        if (++buf == NSTG) buf = 0;
    }
    __syncthreads();

    // ---------------- epilogue ----------------
    if (stage == 0) {
        const float scale = powf(16.0f / logf(257.0f), alpha[0]);
#pragma unroll
        for (int im = 0; im < 2; im++) {
#pragma unroll
            for (int ip8 = 0; ip8 < 8; ip8++) {
                const int cl = wn * 64 + ip8 * 8 + 2 * (lane & 3);
                const float wq0 = s_wsq[cl], wq1 = s_wsq[cl + 1];
                const float* c = acc[im][ip8];
#pragma unroll
                for (int s = 0; s < 2; s++) {
                    const int pl = wm * 32 + im * 16 + (lane >> 2) + 8 * s;
                    const int p  = ctaM * 128 + pl;
                    const float psqv = s_psq[pl];
                    const float f0 = c[2 * s], f1 = c[2 * s + 1];
                    const float y0 = scale * f0 * f0 / (psqv + wq0 - 2.f * f0 + EPSV);
                    const float y1 = scale * f1 * f1 / (psqv + wq1 - 2.f * f1 + EPSV);
                    const size_t oi = (size_t)p * 128 + ((ctaN * 128 + cl) >> 1);
                    ((uint32_t*)g_yhi)[oi] =
                        (uint32_t)__half_as_ushort(__float2half(y0)) |
                        ((uint32_t)__half_as_ushort(__float2half(y1)) << 16);
                }
            }
        }
    } else {
        float* sy = (float*)dsm;
#pragma unroll
        for (int im = 0; im < 2; im++) {
#pragma unroll
            for (int ip8 = 0; ip8 < 8; ip8++) {
                const int cl = wn * 64 + ip8 * 8 + 2 * (lane & 3);
                const float* c = acc[im][ip8];
#pragma unroll
                for (int s = 0; s < 2; s++) {
                    const int pl = wm * 32 + im * 16 + (lane >> 2) + 8 * s;
                    sy[cl * 132 + pl]       = c[2 * s];
                    sy[(cl + 1) * 132 + pl] = c[2 * s + 1];
                }
            }
        }
        __syncthreads();
        for (int i = t; i < 128 * 128; i += 256) {
            const int col = i >> 7, q = i & 127;
            const int p = ctaM * 128 + q;
            const int n = p / 784, rem = p - n * 784;
            out[(size_t)n * 200704 + (size_t)(ctaN * 128 + col) * 784 + rem] =
                sy[col * 132 + q];
        }
    }
}

// ---------------------------------------------------------------- launch
extern "C" void kernel_launch(void* const* d_in, const int* in_sizes, int n_in,
                              void* d_out, int out_size) {
    const float* x       = (const float*)d_in[0];
    const float* w_yat   = (const float*)d_in[1];
    const float* alpha   = (const float*)d_in[2];
    const float* w_lin   = (const float*)d_in[3];
    const float* w_short = (const float*)d_in[4];
    float* out = (float*)d_out;

    cudaFuncSetAttribute(gemm_kernel, cudaFuncAttributeMaxDynamicSharedMemorySize, DYN_SMEM);

    prep_x  <<<dim3(56, 32), 256>>>(x);
    prep_psq<<<dim3(28, 32), 28>>>();
    prep_wA <<<256, 256>>>(w_yat);
    prep_wB <<<256, 256>>>(w_lin, w_short);

    dim3 grid(196, 2);
    gemm_kernel<<<grid, 256, DYN_SMEM>>>(0, alpha, out);   // YAT -> g_yhi
    gemm_kernel<<<grid, 256, DYN_SMEM>>>(1, alpha, out);   // lin + shortcut -> out
}

// round 13
// speedup vs baseline: 1.0434x; 1.0363x over previous
#include <cuda_runtime.h>
#include <cuda_fp16.h>
#include <cstdint>

// ---------------------------------------------------------------- constants
#define EPSV 0.007f
#define NPIX 25088              // 32*28*28 = 196 * 128
#define KA   1152
#define KB   2432               // 9*256 + 128 shortcut
#define NKA  36
#define NKB  76

#define ROWB      80            // padded bytes per 32-fp16 k-row
#define OFF_B     10240         // A: 128 rows * 80B, then B: 128 rows * 80B
#define STAGE_SZ  20480
#define NSTG      4
#define DYN_SMEM  81920         // 4*STAGE_SZ; >= epilogue 128*132*4=67584

// ---------------------------------------------------------------- globals
__device__ __align__(256) __half g_xhi[(size_t)32 * 56 * 56 * 128];
__device__ __align__(256) __half g_yhi[(size_t)NPIX * 256];
__device__ __align__(256) float g_xs2[32 * 56 * 56];
__device__ __align__(256) float g_psq[NPIX];
__device__ __align__(256) __half g_wA[256 * KA];
__device__ __align__(256) __half g_wB[256 * KB];
__device__ __align__(256) float g_wsq[256];

// ---------------------------------------------------------------- ptx utils
__device__ __forceinline__ uint32_t smem_u32(const void* p) {
    return (uint32_t)__cvta_generic_to_shared(p);
}
__device__ __forceinline__ void cpa16(uint32_t dst, const void* src, uint32_t sz) {
    asm volatile("cp.async.cg.shared.global [%0], [%1], 16, %2;"
                 :: "r"(dst), "l"(src), "r"(sz) : "memory");
}
#define CP_COMMIT() asm volatile("cp.async.commit_group;" ::: "memory")
#define CP_WAIT2()  asm volatile("cp.async.wait_group 2;" ::: "memory")

#define LDSM4(r0, r1, r2, r3, addr) \
    asm volatile("ldmatrix.sync.aligned.m8n8.x4.shared.b16 {%0,%1,%2,%3}, [%4];" \
                 : "=r"(r0), "=r"(r1), "=r"(r2), "=r"(r3) : "r"(addr))

#define MMAF16(C, A, B0, B1) \
    asm volatile("mma.sync.aligned.m16n8k16.row.col.f32.f16.f16.f32 " \
                 "{%0,%1,%2,%3}, {%4,%5,%6,%7}, {%8,%9}, {%0,%1,%2,%3};" \
                 : "+f"((C)[0]), "+f"((C)[1]), "+f"((C)[2]), "+f"((C)[3]) \
                 : "r"((A)[0]), "r"((A)[1]), "r"((A)[2]), "r"((A)[3]), \
                   "r"(B0), "r"(B1))

// ---------------------------------------------------------------- prep
__global__ __launch_bounds__(256) void prep_x(const float* __restrict__ x) {
    __shared__ float s[128][57];
    __shared__ float s2p[56][4];
    const int h = blockIdx.x, n = blockIdx.y;
    const float* xb = x + ((size_t)n * 128 * 56 + h) * 56;
    for (int idx = threadIdx.x; idx < 128 * 56; idx += 256) {
        int ci = idx / 56, wi = idx - 56 * ci;
        s[ci][wi] = xb[(size_t)ci * 3136 + wi];
    }
    __syncthreads();
    for (int idx = threadIdx.x; idx < 56 * 128; idx += 256) {
        int wi = idx >> 7, ci = idx & 127;
        g_xhi[((size_t)(n * 56 + h) * 56 + wi) * 128 + ci] = __float2half(s[ci][wi]);
    }
    if (threadIdx.x < 224) {
        int wi = threadIdx.x >> 2, q = threadIdx.x & 3;
        float a = 0.f;
        for (int ci = q * 32; ci < q * 32 + 32; ci++) { float v = s[ci][wi]; a += v * v; }
        s2p[wi][q] = a;
    }
    __syncthreads();
    if (threadIdx.x < 56) {
        int wi = threadIdx.x;
        g_xs2[(n * 56 + h) * 56 + wi] = s2p[wi][0] + s2p[wi][1] + s2p[wi][2] + s2p[wi][3];
    }
}

__global__ void prep_psq() {
    const int pw = threadIdx.x, ph = blockIdx.x, n = blockIdx.y;
    float s = 0.f;
    for (int dr = -1; dr <= 1; dr++) {
        int r = 2 * ph + dr;
        if ((unsigned)r >= 56) continue;
        for (int dc = -1; dc <= 1; dc++) {
            int c = 2 * pw + dc;
            if ((unsigned)c >= 56) continue;
            s += g_xs2[(n * 56 + r) * 56 + c];
        }
    }
    g_psq[(n * 28 + ph) * 28 + pw] = s;
}

// fused weight prep: blocks 0..255 -> w_yat (+wsq); 256..511 -> w_lin+w_short
__global__ __launch_bounds__(256) void prep_w(const float* __restrict__ wy,
                                              const float* __restrict__ wl,
                                              const float* __restrict__ ws) {
    __shared__ float red[256];
    if (blockIdx.x < 256) {
        const int co = blockIdx.x;
        float acc = 0.f;
        for (int k = threadIdx.x; k < KA; k += 256) {
            int kh = k / 384, rem = k - kh * 384, kw = rem >> 7, ci = rem & 127;
            float v = wy[(size_t)co * KA + ci * 9 + kh * 3 + kw];
            g_wA[(size_t)co * KA + k] = __float2half(v);
            acc += v * v;
        }
        red[threadIdx.x] = acc;
        __syncthreads();
        for (int o = 128; o > 0; o >>= 1) {
            if (threadIdx.x < o) red[threadIdx.x] += red[threadIdx.x + o];
            __syncthreads();
        }
        if (threadIdx.x == 0) g_wsq[co] = red[0];
    } else {
        const int co = blockIdx.x - 256;
        for (int k = threadIdx.x; k < 2304; k += 256) {
            int kh = k / 768, rem = k - kh * 768, kw = rem >> 8, ci = rem & 255;
            g_wB[(size_t)co * KB + k] =
                __float2half(wl[(size_t)co * 2304 + ci * 9 + kh * 3 + kw]);
        }
        for (int k = threadIdx.x; k < 128; k += 256)
            g_wB[(size_t)co * KB + 2304 + k] = __float2half(ws[co * 128 + k]);
    }
}

// ---------------------------------------------------------------- k-block fill
// stage buffer: [A 10240][B 10240]; 128 rows x 32 fp16, rows padded to 80B
__device__ __forceinline__ void fill_tile(int stage, int kb, uint32_t sbuf,
                                          int t, int ctaM, int ctaN) {
#pragma unroll
    for (int j = 0; j < 4; j++) {
        const int idx = t + 256 * j;
        const int ch = idx & 3;
        if (idx < 512) {
            const int row = idx >> 2;
            const int p   = ctaM * 128 + row;
            const int n   = p / 784;
            const int rem = p - n * 784;
            const int ph  = rem / 28;
            const int pw  = rem - ph * 28;
            const __half* src;
            uint32_t ok;
            if (stage == 0) {
                int tap = kb >> 2, kh = tap / 3, kw = tap - 3 * (tap / 3);
                int ci0 = (kb & 3) * 32;
                int r = 2 * ph - 1 + kh, c = 2 * pw - 1 + kw;
                bool v = ((unsigned)r < 56) && ((unsigned)c < 56);
                size_t off = v ? ((size_t)((n * 56 + r) * 56 + c) * 128 + ci0) : 0;
                src = g_xhi + off; ok = v ? 16u : 0u;
            } else if (kb < 72) {
                int tap = kb >> 3, kh = tap / 3, kw = tap - 3 * (tap / 3);
                int co0 = (kb & 7) * 32;
                int r = ph - 1 + kh, c = pw - 1 + kw;
                bool v = ((unsigned)r < 28) && ((unsigned)c < 28);
                size_t off = v ? ((size_t)((n * 28 + r) * 28 + c) * 256 + co0) : 0;
                src = g_yhi + off; ok = v ? 16u : 0u;
            } else {
                int ci0 = (kb - 72) * 32;
                size_t off = (size_t)((n * 56 + 2 * ph) * 56 + 2 * pw) * 128 + ci0;
                src = g_xhi + off; ok = 16u;
            }
            cpa16(sbuf + row * ROWB + ch * 16, (const char*)src + ch * 16, ok);
        } else {
            const int widx = idx - 512;          // 0..511
            const int row  = widx >> 2;          // 0..127
            const int co   = ctaN * 128 + row;
            const __half* src = stage ? (g_wB + (size_t)co * KB + kb * 32)
                                      : (g_wA + (size_t)co * KA + kb * 32);
            cpa16(sbuf + OFF_B + row * ROWB + ch * 16,
                  (const char*)src + ch * 16, 16u);
        }
    }
}

// ---------------------------------------------------------------- GEMM kernel
// CTA 128 px x 128 co; 8 warps 4(m) x 2(n); warp tile 32 x 64.
// Single fp16 pass, fp32 accum. 4-stage pipeline, prefetch +3, wait_group 2.
__global__ __launch_bounds__(256, 2)
void gemm_kernel(int stage, const float* __restrict__ alpha, float* __restrict__ out) {
    extern __shared__ __align__(1024) char dsm[];
    __shared__ float s_psq[128];
    __shared__ float s_wsq[128];

    const int t    = threadIdx.x;
    const int lane = t & 31;
    const int w    = t >> 5;
    const int wm   = w & 3;
    const int wn   = w >> 2;
    const int ctaM = blockIdx.x;
    const int ctaN = blockIdx.y;
    const uint32_t sdyn = smem_u32(dsm);

    if (stage == 0 && t < 128) {
        s_psq[t] = g_psq[ctaM * 128 + t];
        s_wsq[t] = g_wsq[ctaN * 128 + t];
    }

    float acc[2][8][4];
#pragma unroll
    for (int a = 0; a < 2; a++)
#pragma unroll
        for (int b = 0; b < 8; b++)
#pragma unroll
            for (int c = 0; c < 4; c++) acc[a][b][c] = 0.f;

    const uint32_t aOff = (uint32_t)(wm * 32 + (lane & 15)) * ROWB + (lane >> 4) * 16;
    const uint32_t bOff = (uint32_t)(wn * 64 + (lane & 7) + ((lane >> 4) << 3)) * ROWB
                        + ((lane >> 3) & 1) * 16;

    const int NK = stage ? NKB : NKA;

    // prologue: 3 k-blocks in flight
    fill_tile(stage, 0, sdyn, t, ctaM, ctaN);                CP_COMMIT();
    fill_tile(stage, 1, sdyn + STAGE_SZ, t, ctaM, ctaN);     CP_COMMIT();
    fill_tile(stage, 2, sdyn + 2 * STAGE_SZ, t, ctaM, ctaN); CP_COMMIT();

    int buf = 0;
    for (int kb = 0; kb < NK; kb++) {
        CP_WAIT2();                 // group kb retired (<=2 younger pending)
        __syncthreads();            // buffer kb visible; compute(kb-1) done

        if (kb + 3 < NK) {
            int nb = buf + 3; if (nb >= NSTG) nb -= NSTG;
            fill_tile(stage, kb + 3, sdyn + nb * STAGE_SZ, t, ctaM, ctaN);
        }
        CP_COMMIT();                // one group per iteration (may be empty)

        const uint32_t sb = sdyn + buf * STAGE_SZ;
#pragma unroll
        for (int kc = 0; kc < 2; kc++) {
            const uint32_t kByte = kc * 32;
            uint32_t ah[2][4];
#pragma unroll
            for (int im = 0; im < 2; im++) {
                uint32_t addr = sb + aOff + im * (16 * ROWB) + kByte;
                LDSM4(ah[im][0], ah[im][1], ah[im][2], ah[im][3], addr);
            }
#pragma unroll
            for (int ip16 = 0; ip16 < 4; ip16++) {
                uint32_t baddr = sb + OFF_B + bOff + ip16 * (16 * ROWB) + kByte;
                uint32_t b0, b1, b2, b3;
                LDSM4(b0, b1, b2, b3, baddr);
#pragma unroll
                for (int im = 0; im < 2; im++) {
                    MMAF16(acc[im][2 * ip16],     ah[im], b0, b1);
                    MMAF16(acc[im][2 * ip16 + 1], ah[im], b2, b3);
                }
            }
        }
        if (++buf == NSTG) buf = 0;
    }
    __syncthreads();

    // ---------------- epilogue ----------------
    if (stage == 0) {
        const float scale = powf(16.0f / logf(257.0f), alpha[0]);
#pragma unroll
        for (int im = 0; im < 2; im++) {
#pragma unroll
            for (int ip8 = 0; ip8 < 8; ip8++) {
                const int cl = wn * 64 + ip8 * 8 + 2 * (lane & 3);
                const float wq0 = s_wsq[cl], wq1 = s_wsq[cl + 1];
                const float* c = acc[im][ip8];
#pragma unroll
                for (int s = 0; s < 2; s++) {
                    const int pl = wm * 32 + im * 16 + (lane >> 2) + 8 * s;
                    const int p  = ctaM * 128 + pl;
                    const float psqv = s_psq[pl];
                    const float f0 = c[2 * s], f1 = c[2 * s + 1];
                    const float y0 = scale * f0 * f0 / (psqv + wq0 - 2.f * f0 + EPSV);
                    const float y1 = scale * f1 * f1 / (psqv + wq1 - 2.f * f1 + EPSV);
                    const size_t oi = (size_t)p * 128 + ((ctaN * 128 + cl) >> 1);
                    ((uint32_t*)g_yhi)[oi] =
                        (uint32_t)__half_as_ushort(__float2half(y0)) |
                        ((uint32_t)__half_as_ushort(__float2half(y1)) << 16);
                }
            }
        }
    } else {
        float* sy = (float*)dsm;
#pragma unroll
        for (int im = 0; im < 2; im++) {
#pragma unroll
            for (int ip8 = 0; ip8 < 8; ip8++) {
                const int cl = wn * 64 + ip8 * 8 + 2 * (lane & 3);
                const float* c = acc[im][ip8];
#pragma unroll
                for (int s = 0; s < 2; s++) {
                    const int pl = wm * 32 + im * 16 + (lane >> 2) + 8 * s;
                    sy[cl * 132 + pl]       = c[2 * s];
                    sy[(cl + 1) * 132 + pl] = c[2 * s + 1];
                }
            }
        }
        __syncthreads();
        for (int i = t; i < 128 * 128; i += 256) {
            const int col = i >> 7, q = i & 127;
            const int p = ctaM * 128 + q;
            const int n = p / 784, rem = p - n * 784;
            out[(size_t)n * 200704 + (size_t)(ctaN * 128 + col) * 784 + rem] =
                sy[col * 132 + q];
        }
    }
}

// ---------------------------------------------------------------- launch
extern "C" void kernel_launch(void* const* d_in, const int* in_sizes, int n_in,
                              void* d_out, int out_size) {
    const float* x       = (const float*)d_in[0];
    const float* w_yat   = (const float*)d_in[1];
    const float* alpha   = (const float*)d_in[2];
    const float* w_lin   = (const float*)d_in[3];
    const float* w_short = (const float*)d_in[4];
    float* out = (float*)d_out;

    cudaFuncSetAttribute(gemm_kernel, cudaFuncAttributeMaxDynamicSharedMemorySize, DYN_SMEM);

    // order chosen so the ncu capture slot (previously launch #4) hits gemm0
    prep_x  <<<dim3(56, 32), 256>>>(x);
    prep_w  <<<512, 256>>>(w_yat, w_lin, w_short);
    prep_psq<<<dim3(28, 32), 28>>>();

    dim3 grid(196, 2);
    gemm_kernel<<<grid, 256, DYN_SMEM>>>(0, alpha, out);   // YAT -> g_yhi
    gemm_kernel<<<grid, 256, DYN_SMEM>>>(1, alpha, out);   // lin + shortcut -> out
}